// round 1
// baseline (speedup 1.0000x reference)
#include <cuda_runtime.h>
#include <math.h>

#define TABLE_SIZE 524288
#define NUM_LEVELS 16
#define N_POINTS   1048576
#define TBL_TOTAL  (TABLE_SIZE * NUM_LEVELS)   // 8388608
#define HMASK      (TABLE_SIZE - 1)
#define P2         2654435761u
#define P3         805459861u

// 64 MB static scratch: feature-interleaved copy of the hash table.
__device__ float2 g_tbl[TBL_TOTAL];

struct ScalArr { float s[NUM_LEVELS]; };

// ---------------------------------------------------------------------------
// Repack: hash_table (2, 8388608) -> float2[8388608]. Fully coalesced streams.
// ---------------------------------------------------------------------------
__global__ __launch_bounds__(256) void repack_kernel(const float* __restrict__ ht) {
    int i = blockIdx.x * blockDim.x + threadIdx.x;
    float a = __ldg(ht + i);
    float b = __ldg(ht + i + TBL_TOTAL);
    g_tbl[i] = make_float2(a, b);
}

// Scrambled weight: fracflat[k] = frac( coord[k%3] * scaling[k/3] )
// k is compile-time after full unroll, so the selects fold away.
__device__ __forceinline__ float fracw(float vx, float vy, float vz,
                                       const float* __restrict__ s, int k) {
    int d = k % 3;
    float v = (d == 0) ? vx : ((d == 1) ? vy : vz);
    float t = v * s[k / 3];
    return t - floorf(t);
}

// ---------------------------------------------------------------------------
// Main encoding kernel: one thread per point, 16 levels fully unrolled.
// ---------------------------------------------------------------------------
__global__ __launch_bounds__(256) void hashenc_kernel(
    const float* __restrict__ x,
    float* __restrict__ out,
    ScalArr sc)
{
    int n = blockIdx.x * blockDim.x + threadIdx.x;
    if (n >= N_POINTS) return;

    float vx = x[3 * n + 0];
    float vy = x[3 * n + 1];
    float vz = x[3 * n + 2];

    float res[2 * NUM_LEVELS];

    #pragma unroll
    for (int L = 0; L < NUM_LEVELS; ++L) {
        float s  = sc.s[L];
        float sx = vx * s, sy = vy * s, sz = vz * s;

        unsigned fx = (unsigned)(int)floorf(sx);
        unsigned cx = (unsigned)(int)ceilf(sx);
        unsigned fy = (unsigned)(int)floorf(sy);
        unsigned cy = (unsigned)(int)ceilf(sy);
        unsigned fz = (unsigned)(int)floorf(sz);
        unsigned cz = (unsigned)(int)ceilf(sz);

        unsigned hyf = fy * P2, hyc = cy * P2;
        unsigned hzf = fz * P3, hzc = cz * P3;

        const float2* __restrict__ tbl = g_tbl + (size_t)L * TABLE_SIZE;

        // SEL order: 0:(c,c,c) 1:(c,c,f) 2:(c,f,c) 3:(f,c,c)
        //            4:(c,f,f) 5:(f,c,f) 6:(f,f,c) 7:(f,f,f)
        float2 F0 = __ldg(tbl + ((cx ^ hyc ^ hzc) & HMASK));
        float2 F1 = __ldg(tbl + ((cx ^ hyc ^ hzf) & HMASK));
        float2 F2 = __ldg(tbl + ((cx ^ hyf ^ hzc) & HMASK));
        float2 F3 = __ldg(tbl + ((fx ^ hyc ^ hzc) & HMASK));
        float2 F4 = __ldg(tbl + ((cx ^ hyf ^ hzf) & HMASK));
        float2 F5 = __ldg(tbl + ((fx ^ hyc ^ hzf) & HMASK));
        float2 F6 = __ldg(tbl + ((fx ^ hyf ^ hzc) & HMASK));
        float2 F7 = __ldg(tbl + ((fx ^ hyf ^ hzf) & HMASK));

        // Scrambled trilinear weights (reference reshapes (N,16,3)->(N,3,16)
        // without transpose, so weights come from other levels/dims).
        float wx = fracw(vx, vy, vz, sc.s, L);
        float wy = fracw(vx, vy, vz, sc.s, 16 + L);
        float wz = fracw(vx, vy, vz, sc.s, 32 + L);
        float qx = 1.0f - wx, qy = 1.0f - wy, qz = 1.0f - wz;

        // feature 0
        {
            float f03 = F0.x * wx + F3.x * qx;
            float f12 = F1.x * wx + F2.x * qx;
            float f56 = F5.x * wx + F6.x * qx;
            float f47 = F4.x * wx + F7.x * qx;
            float a   = f03 * wy + f12 * qy;
            float b   = f47 * wy + f56 * qy;
            res[2 * L + 0] = a * wz + b * qz;
        }
        // feature 1
        {
            float f03 = F0.y * wx + F3.y * qx;
            float f12 = F1.y * wx + F2.y * qx;
            float f56 = F5.y * wx + F6.y * qx;
            float f47 = F4.y * wx + F7.y * qx;
            float a   = f03 * wy + f12 * qy;
            float b   = f47 * wy + f56 * qy;
            res[2 * L + 1] = a * wz + b * qz;
        }
    }

    // 32 contiguous floats per point -> 8 x STG.128
    float4* o = (float4*)(out + (size_t)n * (2 * NUM_LEVELS));
    #pragma unroll
    for (int i = 0; i < 8; ++i)
        o[i] = make_float4(res[4 * i + 0], res[4 * i + 1],
                           res[4 * i + 2], res[4 * i + 3]);
}

// ---------------------------------------------------------------------------
// Host: replicate numpy's SCALINGS bit-for-bit with double libm.
// ---------------------------------------------------------------------------
static void compute_scalings(ScalArr& a) {
    double growth = exp((log(2048.0) - log(16.0)) / 15.0);
    for (int l = 0; l < NUM_LEVELS; ++l)
        a.s[l] = (float)floor(16.0 * pow(growth, (double)l));
}

extern "C" void kernel_launch(void* const* d_in, const int* in_sizes, int n_in,
                              void* d_out, int out_size) {
    const float* x  = (const float*)d_in[0];
    const float* ht = (const float*)d_in[1];
    float* out = (float*)d_out;

    ScalArr sc;
    compute_scalings(sc);

    repack_kernel<<<TBL_TOTAL / 256, 256>>>(ht);
    hashenc_kernel<<<N_POINTS / 256, 256>>>(x, out, sc);
}

// round 2
// speedup vs baseline: 1.2038x; 1.2038x over previous
#include <cuda_runtime.h>
#include <math.h>

#define TABLE_SIZE 524288
#define NUM_LEVELS 16
#define N_POINTS   1048576
#define TBL_TOTAL  (TABLE_SIZE * NUM_LEVELS)   // 8388608
#define HMASK      (TABLE_SIZE - 1)
#define P2         2654435761u
#define P3         805459861u

#define MORT_BITS  5
#define NBUCK      32768   // 2^(3*MORT_BITS)

// Static scratch (allocation-guard safe):
__device__ float2 g_tbl[TBL_TOTAL];      // 64 MB feature-interleaved table
__device__ float4 g_xs[N_POINTS];        // 16 MB sorted points (.w = orig idx)
__device__ int    g_hist[NBUCK];
__device__ int    g_cursor[NBUCK];

struct ScalArr { float s[NUM_LEVELS]; };

// ---------------------------------------------------------------------------
// Repack: hash_table (2, 8388608) -> float2[8388608]. Fully coalesced.
// ---------------------------------------------------------------------------
__global__ __launch_bounds__(256) void repack_kernel(const float* __restrict__ ht) {
    int i = blockIdx.x * blockDim.x + threadIdx.x;
    float a = __ldg(ht + i);
    float b = __ldg(ht + i + TBL_TOTAL);
    g_tbl[i] = make_float2(a, b);
}

// ---------------------------------------------------------------------------
// Morton bucket (5 bits/dim -> 15-bit code)
// ---------------------------------------------------------------------------
__device__ __forceinline__ unsigned mort5(unsigned v) {
    unsigned m = 0;
    #pragma unroll
    for (int b = 0; b < MORT_BITS; ++b) m |= ((v >> b) & 1u) << (3 * b);
    return m;
}

__device__ __forceinline__ unsigned bucket_of(float x, float y, float z) {
    unsigned ix = min(31u, (unsigned)(int)(x * 32.0f));
    unsigned iy = min(31u, (unsigned)(int)(y * 32.0f));
    unsigned iz = min(31u, (unsigned)(int)(z * 32.0f));
    return mort5(ix) | (mort5(iy) << 1) | (mort5(iz) << 2);
}

__global__ __launch_bounds__(256) void zero_kernel() {
    int i = blockIdx.x * blockDim.x + threadIdx.x;
    if (i < NBUCK) g_hist[i] = 0;
}

__global__ __launch_bounds__(256) void hist_kernel(const float* __restrict__ x) {
    int n = blockIdx.x * blockDim.x + threadIdx.x;
    float vx = x[3 * n + 0], vy = x[3 * n + 1], vz = x[3 * n + 2];
    atomicAdd(&g_hist[bucket_of(vx, vy, vz)], 1);
}

// Single-block exclusive scan of g_hist -> g_cursor (32768 elems)
__global__ __launch_bounds__(1024) void scan_kernel() {
    __shared__ int sh[1024];
    int t = threadIdx.x;
    int base = t * (NBUCK / 1024);
    int local[NBUCK / 1024];
    int s = 0;
    #pragma unroll
    for (int i = 0; i < NBUCK / 1024; ++i) { local[i] = g_hist[base + i]; s += local[i]; }
    sh[t] = s;
    __syncthreads();
    for (int off = 1; off < 1024; off <<= 1) {
        int v = (t >= off) ? sh[t - off] : 0;
        __syncthreads();
        sh[t] += v;
        __syncthreads();
    }
    int run = (t == 0) ? 0 : sh[t - 1];
    #pragma unroll
    for (int i = 0; i < NBUCK / 1024; ++i) { g_cursor[base + i] = run; run += local[i]; }
}

__global__ __launch_bounds__(256) void scatter_kernel(const float* __restrict__ x) {
    int n = blockIdx.x * blockDim.x + threadIdx.x;
    float vx = x[3 * n + 0], vy = x[3 * n + 1], vz = x[3 * n + 2];
    unsigned b = bucket_of(vx, vy, vz);
    int pos = atomicAdd(&g_cursor[b], 1);
    g_xs[pos] = make_float4(vx, vy, vz, __int_as_float(n));
}

// ---------------------------------------------------------------------------
// Scrambled weight: fracflat[k] = frac( coord[k%3] * scaling[k/3] )
// ---------------------------------------------------------------------------
__device__ __forceinline__ float fracw(float vx, float vy, float vz,
                                       const float* __restrict__ s, int k) {
    int d = k % 3;
    float v = (d == 0) ? vx : ((d == 1) ? vy : vz);
    float t = v * s[k / 3];
    return t - floorf(t);
}

// ---------------------------------------------------------------------------
// Main encoding kernel: one thread per (Morton-sorted) point.
// ---------------------------------------------------------------------------
__global__ __launch_bounds__(256) void hashenc_kernel(
    float* __restrict__ out,
    ScalArr sc)
{
    int n = blockIdx.x * blockDim.x + threadIdx.x;

    float4 p = g_xs[n];
    float vx = p.x, vy = p.y, vz = p.z;
    int orig = __float_as_int(p.w);

    float res[2 * NUM_LEVELS];

    #pragma unroll
    for (int L = 0; L < NUM_LEVELS; ++L) {
        float s  = sc.s[L];
        float sx = vx * s, sy = vy * s, sz = vz * s;

        unsigned fx = (unsigned)(int)floorf(sx);
        unsigned cx = (unsigned)(int)ceilf(sx);
        unsigned fy = (unsigned)(int)floorf(sy);
        unsigned cy = (unsigned)(int)ceilf(sy);
        unsigned fz = (unsigned)(int)floorf(sz);
        unsigned cz = (unsigned)(int)ceilf(sz);

        unsigned hyf = fy * P2, hyc = cy * P2;
        unsigned hzf = fz * P3, hzc = cz * P3;

        const float2* __restrict__ tbl = g_tbl + (size_t)L * TABLE_SIZE;

        float2 F0 = __ldg(tbl + ((cx ^ hyc ^ hzc) & HMASK));
        float2 F1 = __ldg(tbl + ((cx ^ hyc ^ hzf) & HMASK));
        float2 F2 = __ldg(tbl + ((cx ^ hyf ^ hzc) & HMASK));
        float2 F3 = __ldg(tbl + ((fx ^ hyc ^ hzc) & HMASK));
        float2 F4 = __ldg(tbl + ((cx ^ hyf ^ hzf) & HMASK));
        float2 F5 = __ldg(tbl + ((fx ^ hyc ^ hzf) & HMASK));
        float2 F6 = __ldg(tbl + ((fx ^ hyf ^ hzc) & HMASK));
        float2 F7 = __ldg(tbl + ((fx ^ hyf ^ hzf) & HMASK));

        float wx = fracw(vx, vy, vz, sc.s, L);
        float wy = fracw(vx, vy, vz, sc.s, 16 + L);
        float wz = fracw(vx, vy, vz, sc.s, 32 + L);
        float qx = 1.0f - wx, qy = 1.0f - wy, qz = 1.0f - wz;

        {
            float f03 = F0.x * wx + F3.x * qx;
            float f12 = F1.x * wx + F2.x * qx;
            float f56 = F5.x * wx + F6.x * qx;
            float f47 = F4.x * wx + F7.x * qx;
            float a   = f03 * wy + f12 * qy;
            float b   = f47 * wy + f56 * qy;
            res[2 * L + 0] = a * wz + b * qz;
        }
        {
            float f03 = F0.y * wx + F3.y * qx;
            float f12 = F1.y * wx + F2.y * qx;
            float f56 = F5.y * wx + F6.y * qx;
            float f47 = F4.y * wx + F7.y * qx;
            float a   = f03 * wy + f12 * qy;
            float b   = f47 * wy + f56 * qy;
            res[2 * L + 1] = a * wz + b * qz;
        }
    }

    // 128B row per point, scattered by original index.
    float4* o = (float4*)(out + (size_t)orig * (2 * NUM_LEVELS));
    #pragma unroll
    for (int i = 0; i < 8; ++i)
        o[i] = make_float4(res[4 * i + 0], res[4 * i + 1],
                           res[4 * i + 2], res[4 * i + 3]);
}

// ---------------------------------------------------------------------------
// Host: replicate numpy's SCALINGS bit-for-bit with double libm.
// ---------------------------------------------------------------------------
static void compute_scalings(ScalArr& a) {
    double growth = exp((log(2048.0) - log(16.0)) / 15.0);
    for (int l = 0; l < NUM_LEVELS; ++l)
        a.s[l] = (float)floor(16.0 * pow(growth, (double)l));
}

extern "C" void kernel_launch(void* const* d_in, const int* in_sizes, int n_in,
                              void* d_out, int out_size) {
    const float* x  = (const float*)d_in[0];
    const float* ht = (const float*)d_in[1];
    float* out = (float*)d_out;

    ScalArr sc;
    compute_scalings(sc);

    repack_kernel<<<TBL_TOTAL / 256, 256>>>(ht);
    zero_kernel<<<NBUCK / 256, 256>>>();
    hist_kernel<<<N_POINTS / 256, 256>>>(x);
    scan_kernel<<<1, 1024>>>();
    scatter_kernel<<<N_POINTS / 256, 256>>>(x);
    hashenc_kernel<<<N_POINTS / 256, 256>>>(out, sc);
}

// round 3
// speedup vs baseline: 1.3151x; 1.0925x over previous
#include <cuda_runtime.h>
#include <math.h>

#define TABLE_SIZE 524288
#define NUM_LEVELS 16
#define N_POINTS   1048576
#define TBL_TOTAL  (TABLE_SIZE * NUM_LEVELS)   // 8388608
#define HMASK      (TABLE_SIZE - 1)
#define P2         2654435761u
#define P3         805459861u

#define MORT_BITS  5
#define NBUCK      32768   // 2^(3*MORT_BITS)
#define SCAN_BLOCKS 32     // 32 blocks x 1024 elems

// Static scratch (allocation-guard safe):
__device__ float2 g_tbl[TBL_TOTAL];      // 64 MB feature-interleaved table
__device__ float4 g_xs[N_POINTS];        // 16 MB sorted points (.w = orig idx)
__device__ int    g_hist[NBUCK];
__device__ int    g_cursor[NBUCK];       // within-chunk exclusive scan -> running cursor
__device__ int    g_bsum[SCAN_BLOCKS];
__device__ int    g_boff[SCAN_BLOCKS];

struct ScalArr { float s[NUM_LEVELS]; };

// ---------------------------------------------------------------------------
// Repack: hash_table (2, 8388608) -> float2[8388608]. Fully coalesced.
// ---------------------------------------------------------------------------
__global__ __launch_bounds__(256) void repack_kernel(const float* __restrict__ ht) {
    int i = blockIdx.x * blockDim.x + threadIdx.x;
    float a = __ldg(ht + i);
    float b = __ldg(ht + i + TBL_TOTAL);
    g_tbl[i] = make_float2(a, b);
}

// ---------------------------------------------------------------------------
// Morton bucket (5 bits/dim -> 15-bit code)
// ---------------------------------------------------------------------------
__device__ __forceinline__ unsigned mort5(unsigned v) {
    unsigned m = 0;
    #pragma unroll
    for (int b = 0; b < MORT_BITS; ++b) m |= ((v >> b) & 1u) << (3 * b);
    return m;
}

__device__ __forceinline__ unsigned bucket_of(float x, float y, float z) {
    unsigned ix = min(31u, (unsigned)(int)(x * 32.0f));
    unsigned iy = min(31u, (unsigned)(int)(y * 32.0f));
    unsigned iz = min(31u, (unsigned)(int)(z * 32.0f));
    return mort5(ix) | (mort5(iy) << 1) | (mort5(iz) << 2);
}

__global__ __launch_bounds__(256) void hist_kernel(const float* __restrict__ x) {
    int n = blockIdx.x * blockDim.x + threadIdx.x;
    float vx = x[3 * n + 0], vy = x[3 * n + 1], vz = x[3 * n + 2];
    atomicAdd(&g_hist[bucket_of(vx, vy, vz)], 1);
}

// ---------------------------------------------------------------------------
// Hierarchical scan. Stage A: 32 blocks, each scans 1024 elems of g_hist
// into g_cursor (exclusive within block) and writes its block sum.
// ---------------------------------------------------------------------------
__global__ __launch_bounds__(1024) void scanA_kernel() {
    __shared__ int sh[1024];
    int t = threadIdx.x;
    int i = blockIdx.x * 1024 + t;
    int v = g_hist[i];
    sh[t] = v;
    __syncthreads();
    #pragma unroll
    for (int off = 1; off < 1024; off <<= 1) {
        int u = (t >= off) ? sh[t - off] : 0;
        __syncthreads();
        sh[t] += u;
        __syncthreads();
    }
    g_cursor[i] = sh[t] - v;                 // exclusive within block
    if (t == 1023) g_bsum[blockIdx.x] = sh[t];
}

// Stage B: one warp scans the 32 block sums (exclusive).
__global__ void scanB_kernel() {
    int t = threadIdx.x;   // 32 threads
    int v = g_bsum[t];
    int s = v;
    #pragma unroll
    for (int off = 1; off < 32; off <<= 1) {
        int u = __shfl_up_sync(0xFFFFFFFF, s, off);
        if (t >= off) s += u;
    }
    g_boff[t] = s - v;     // exclusive
}

__global__ __launch_bounds__(256) void scatter_kernel(const float* __restrict__ x) {
    int n = blockIdx.x * blockDim.x + threadIdx.x;
    float vx = x[3 * n + 0], vy = x[3 * n + 1], vz = x[3 * n + 2];
    unsigned b = bucket_of(vx, vy, vz);
    int pos = g_boff[b >> 10] + atomicAdd(&g_cursor[b], 1);
    g_xs[pos] = make_float4(vx, vy, vz, __int_as_float(n));
}

// ---------------------------------------------------------------------------
// Scrambled weight: fracflat[k] = frac( coord[k%3] * scaling[k/3] )
// ---------------------------------------------------------------------------
__device__ __forceinline__ float fracw(float vx, float vy, float vz,
                                       const float* __restrict__ s, int k) {
    int d = k % 3;
    float v = (d == 0) ? vx : ((d == 1) ? vy : vz);
    float t = v * s[k / 3];
    return t - floorf(t);
}

// ---------------------------------------------------------------------------
// Main encoding kernel: one thread per (Morton-sorted) point.
// ---------------------------------------------------------------------------
__global__ __launch_bounds__(256) void hashenc_kernel(
    float* __restrict__ out,
    ScalArr sc)
{
    int n = blockIdx.x * blockDim.x + threadIdx.x;

    float4 p = g_xs[n];
    float vx = p.x, vy = p.y, vz = p.z;
    int orig = __float_as_int(p.w);

    float res[2 * NUM_LEVELS];

    #pragma unroll
    for (int L = 0; L < NUM_LEVELS; ++L) {
        float s  = sc.s[L];
        float sx = vx * s, sy = vy * s, sz = vz * s;

        unsigned fx = (unsigned)(int)floorf(sx);
        unsigned cx = (unsigned)(int)ceilf(sx);
        unsigned fy = (unsigned)(int)floorf(sy);
        unsigned cy = (unsigned)(int)ceilf(sy);
        unsigned fz = (unsigned)(int)floorf(sz);
        unsigned cz = (unsigned)(int)ceilf(sz);

        unsigned hyf = fy * P2, hyc = cy * P2;
        unsigned hzf = fz * P3, hzc = cz * P3;

        const float2* __restrict__ tbl = g_tbl + (size_t)L * TABLE_SIZE;

        float2 F0 = __ldg(tbl + ((cx ^ hyc ^ hzc) & HMASK));
        float2 F1 = __ldg(tbl + ((cx ^ hyc ^ hzf) & HMASK));
        float2 F2 = __ldg(tbl + ((cx ^ hyf ^ hzc) & HMASK));
        float2 F3 = __ldg(tbl + ((fx ^ hyc ^ hzc) & HMASK));
        float2 F4 = __ldg(tbl + ((cx ^ hyf ^ hzf) & HMASK));
        float2 F5 = __ldg(tbl + ((fx ^ hyc ^ hzf) & HMASK));
        float2 F6 = __ldg(tbl + ((fx ^ hyf ^ hzc) & HMASK));
        float2 F7 = __ldg(tbl + ((fx ^ hyf ^ hzf) & HMASK));

        float wx = fracw(vx, vy, vz, sc.s, L);
        float wy = fracw(vx, vy, vz, sc.s, 16 + L);
        float wz = fracw(vx, vy, vz, sc.s, 32 + L);
        float qx = 1.0f - wx, qy = 1.0f - wy, qz = 1.0f - wz;

        {
            float f03 = F0.x * wx + F3.x * qx;
            float f12 = F1.x * wx + F2.x * qx;
            float f56 = F5.x * wx + F6.x * qx;
            float f47 = F4.x * wx + F7.x * qx;
            float a   = f03 * wy + f12 * qy;
            float b   = f47 * wy + f56 * qy;
            res[2 * L + 0] = a * wz + b * qz;
        }
        {
            float f03 = F0.y * wx + F3.y * qx;
            float f12 = F1.y * wx + F2.y * qx;
            float f56 = F5.y * wx + F6.y * qx;
            float f47 = F4.y * wx + F7.y * qx;
            float a   = f03 * wy + f12 * qy;
            float b   = f47 * wy + f56 * qy;
            res[2 * L + 1] = a * wz + b * qz;
        }
    }

    // 128B row per point, scattered by original index.
    float4* o = (float4*)(out + (size_t)orig * (2 * NUM_LEVELS));
    #pragma unroll
    for (int i = 0; i < 8; ++i)
        o[i] = make_float4(res[4 * i + 0], res[4 * i + 1],
                           res[4 * i + 2], res[4 * i + 3]);
}

// ---------------------------------------------------------------------------
// Host: replicate numpy's SCALINGS bit-for-bit with double libm.
// ---------------------------------------------------------------------------
static void compute_scalings(ScalArr& a) {
    double growth = exp((log(2048.0) - log(16.0)) / 15.0);
    for (int l = 0; l < NUM_LEVELS; ++l)
        a.s[l] = (float)floor(16.0 * pow(growth, (double)l));
}

extern "C" void kernel_launch(void* const* d_in, const int* in_sizes, int n_in,
                              void* d_out, int out_size) {
    const float* x  = (const float*)d_in[0];
    const float* ht = (const float*)d_in[1];
    float* out = (float*)d_out;

    ScalArr sc;
    compute_scalings(sc);

    void* hist_ptr = nullptr;
    cudaGetSymbolAddress(&hist_ptr, g_hist);
    cudaMemsetAsync(hist_ptr, 0, NBUCK * sizeof(int));

    repack_kernel<<<TBL_TOTAL / 256, 256>>>(ht);
    hist_kernel<<<N_POINTS / 256, 256>>>(x);
    scanA_kernel<<<SCAN_BLOCKS, 1024>>>();
    scanB_kernel<<<1, 32>>>();
    scatter_kernel<<<N_POINTS / 256, 256>>>(x);
    hashenc_kernel<<<N_POINTS / 256, 256>>>(out, sc);
}

// round 4
// speedup vs baseline: 1.3495x; 1.0261x over previous
#include <cuda_runtime.h>
#include <math.h>

#define TABLE_SIZE 524288
#define NUM_LEVELS 16
#define N_POINTS   1048576
#define TBL_TOTAL  (TABLE_SIZE * NUM_LEVELS)   // 8388608
#define HMASK      (TABLE_SIZE - 1)
#define P2         2654435761u
#define P3         805459861u

#define MORT_BITS  5
#define NBUCK      32768    // 2^(3*MORT_BITS)
#define SCAN_BLOCKS 32      // 32 scan blocks x 1024 elems

// Repack work split across the three sort-phase kernels (block-equivalents
// of 256 threads; combo2 uses 1024-thread blocks = 4 equivalents each).
#define HIST_BLOCKS   4096                 // N_POINTS/256
#define SCAT_BLOCKS   4096
#define R1_BLOCKS     12288                // elems [0, 12288*256)
#define R2_BLOCKS1024 3072                 // elems [OFF2, +3072*1024)
#define R3_BLOCKS     8192                 // elems [OFF3, +8192*256)
#define R_OFF2        (R1_BLOCKS * 256)            // 3145728
#define R_OFF3        (R_OFF2 + R2_BLOCKS1024 * 1024) // 6291456

// Static scratch (allocation-guard safe; zero-initialized at load):
__device__ float2 g_tbl[TBL_TOTAL];      // 64 MB feature-interleaved table
__device__ float4 g_xs[N_POINTS];        // 16 MB sorted points (.w = orig idx)
__device__ int    g_hist[NBUCK];
__device__ int    g_cursor[NBUCK];       // within-chunk exclusive scan -> cursor
__device__ int    g_bsum[SCAN_BLOCKS];

struct ScalArr { float s[NUM_LEVELS]; };

// ---------------------------------------------------------------------------
// Repack helper: one float2 per thread at table element index i.
// ---------------------------------------------------------------------------
__device__ __forceinline__ void repack_one(const float* __restrict__ ht, int i) {
    float a = __ldg(ht + i);
    float b = __ldg(ht + i + TBL_TOTAL);
    g_tbl[i] = make_float2(a, b);
}

// ---------------------------------------------------------------------------
// Morton bucket (5 bits/dim -> 15-bit code)
// ---------------------------------------------------------------------------
__device__ __forceinline__ unsigned mort5(unsigned v) {
    unsigned m = 0;
    #pragma unroll
    for (int b = 0; b < MORT_BITS; ++b) m |= ((v >> b) & 1u) << (3 * b);
    return m;
}

__device__ __forceinline__ unsigned bucket_of(float x, float y, float z) {
    unsigned ix = min(31u, (unsigned)(int)(x * 32.0f));
    unsigned iy = min(31u, (unsigned)(int)(y * 32.0f));
    unsigned iz = min(31u, (unsigned)(int)(z * 32.0f));
    return mort5(ix) | (mort5(iy) << 1) | (mort5(iz) << 2);
}

// ---------------------------------------------------------------------------
// Phase 1: histogram + repack part 1 (co-scheduled on one grid).
// ---------------------------------------------------------------------------
__global__ __launch_bounds__(256) void combo1_kernel(const float* __restrict__ x,
                                                     const float* __restrict__ ht) {
    int b = blockIdx.x;
    if (b < HIST_BLOCKS) {
        int n = b * 256 + threadIdx.x;
        float vx = x[3 * n + 0], vy = x[3 * n + 1], vz = x[3 * n + 2];
        atomicAdd(&g_hist[bucket_of(vx, vy, vz)], 1);
    } else {
        repack_one(ht, (b - HIST_BLOCKS) * 256 + threadIdx.x);
    }
}

// ---------------------------------------------------------------------------
// Phase 2: per-chunk scan (+ zero g_hist for next replay) + repack part 2.
// ---------------------------------------------------------------------------
__global__ __launch_bounds__(1024) void combo2_kernel(const float* __restrict__ ht) {
    int bid = blockIdx.x;
    int t = threadIdx.x;
    if (bid < SCAN_BLOCKS) {
        __shared__ int sh[1024];
        int i = bid * 1024 + t;
        int v = g_hist[i];
        g_hist[i] = 0;                        // reset for next graph replay
        sh[t] = v;
        __syncthreads();
        #pragma unroll
        for (int off = 1; off < 1024; off <<= 1) {
            int u = (t >= off) ? sh[t - off] : 0;
            __syncthreads();
            sh[t] += u;
            __syncthreads();
        }
        g_cursor[i] = sh[t] - v;              // exclusive within chunk
        if (t == 1023) g_bsum[bid] = sh[t];
    } else {
        repack_one(ht, R_OFF2 + (bid - SCAN_BLOCKS) * 1024 + t);
    }
}

// ---------------------------------------------------------------------------
// Phase 3: scatter (with inline top-level scan of the 32 chunk sums)
//          + repack part 3.
// ---------------------------------------------------------------------------
__global__ __launch_bounds__(256) void combo3_kernel(const float* __restrict__ x,
                                                     const float* __restrict__ ht) {
    int bid = blockIdx.x;
    if (bid < SCAT_BLOCKS) {
        __shared__ int sh_boff[SCAN_BLOCKS];
        if (threadIdx.x < 32) {
            int v = g_bsum[threadIdx.x];
            int s = v;
            #pragma unroll
            for (int off = 1; off < 32; off <<= 1) {
                int u = __shfl_up_sync(0xFFFFFFFF, s, off);
                if ((int)threadIdx.x >= off) s += u;
            }
            sh_boff[threadIdx.x] = s - v;     // exclusive scan of chunk sums
        }
        __syncthreads();
        int n = bid * 256 + threadIdx.x;
        float vx = x[3 * n + 0], vy = x[3 * n + 1], vz = x[3 * n + 2];
        unsigned b = bucket_of(vx, vy, vz);
        int pos = sh_boff[b >> 10] + atomicAdd(&g_cursor[b], 1);
        g_xs[pos] = make_float4(vx, vy, vz, __int_as_float(n));
    } else {
        repack_one(ht, R_OFF3 + (bid - SCAT_BLOCKS) * 256 + threadIdx.x);
    }
}

// ---------------------------------------------------------------------------
// Scrambled weight: fracflat[k] = frac( coord[k%3] * scaling[k/3] )
// ---------------------------------------------------------------------------
__device__ __forceinline__ float fracw(float vx, float vy, float vz,
                                       const float* __restrict__ s, int k) {
    int d = k % 3;
    float v = (d == 0) ? vx : ((d == 1) ? vy : vz);
    float t = v * s[k / 3];
    return t - floorf(t);
}

// ---------------------------------------------------------------------------
// Main encoding kernel: one thread per (Morton-sorted) point.
// ---------------------------------------------------------------------------
__global__ __launch_bounds__(256) void hashenc_kernel(
    float* __restrict__ out,
    ScalArr sc)
{
    int n = blockIdx.x * blockDim.x + threadIdx.x;

    float4 p = g_xs[n];
    float vx = p.x, vy = p.y, vz = p.z;
    int orig = __float_as_int(p.w);

    float res[2 * NUM_LEVELS];

    #pragma unroll
    for (int L = 0; L < NUM_LEVELS; ++L) {
        float s  = sc.s[L];
        float sx = vx * s, sy = vy * s, sz = vz * s;

        unsigned fx = (unsigned)(int)floorf(sx);
        unsigned cx = (unsigned)(int)ceilf(sx);
        unsigned fy = (unsigned)(int)floorf(sy);
        unsigned cy = (unsigned)(int)ceilf(sy);
        unsigned fz = (unsigned)(int)floorf(sz);
        unsigned cz = (unsigned)(int)ceilf(sz);

        unsigned hyf = fy * P2, hyc = cy * P2;
        unsigned hzf = fz * P3, hzc = cz * P3;

        const float2* __restrict__ tbl = g_tbl + (size_t)L * TABLE_SIZE;

        float2 F0 = __ldg(tbl + ((cx ^ hyc ^ hzc) & HMASK));
        float2 F1 = __ldg(tbl + ((cx ^ hyc ^ hzf) & HMASK));
        float2 F2 = __ldg(tbl + ((cx ^ hyf ^ hzc) & HMASK));
        float2 F3 = __ldg(tbl + ((fx ^ hyc ^ hzc) & HMASK));
        float2 F4 = __ldg(tbl + ((cx ^ hyf ^ hzf) & HMASK));
        float2 F5 = __ldg(tbl + ((fx ^ hyc ^ hzf) & HMASK));
        float2 F6 = __ldg(tbl + ((fx ^ hyf ^ hzc) & HMASK));
        float2 F7 = __ldg(tbl + ((fx ^ hyf ^ hzf) & HMASK));

        float wx = fracw(vx, vy, vz, sc.s, L);
        float wy = fracw(vx, vy, vz, sc.s, 16 + L);
        float wz = fracw(vx, vy, vz, sc.s, 32 + L);
        float qx = 1.0f - wx, qy = 1.0f - wy, qz = 1.0f - wz;

        {
            float f03 = F0.x * wx + F3.x * qx;
            float f12 = F1.x * wx + F2.x * qx;
            float f56 = F5.x * wx + F6.x * qx;
            float f47 = F4.x * wx + F7.x * qx;
            float a   = f03 * wy + f12 * qy;
            float b   = f47 * wy + f56 * qy;
            res[2 * L + 0] = a * wz + b * qz;
        }
        {
            float f03 = F0.y * wx + F3.y * qx;
            float f12 = F1.y * wx + F2.y * qx;
            float f56 = F5.y * wx + F6.y * qx;
            float f47 = F4.y * wx + F7.y * qx;
            float a   = f03 * wy + f12 * qy;
            float b   = f47 * wy + f56 * qy;
            res[2 * L + 1] = a * wz + b * qz;
        }
    }

    // 128B row per point, scattered by original index (full-line stores).
    float4* o = (float4*)(out + (size_t)orig * (2 * NUM_LEVELS));
    #pragma unroll
    for (int i = 0; i < 8; ++i)
        o[i] = make_float4(res[4 * i + 0], res[4 * i + 1],
                           res[4 * i + 2], res[4 * i + 3]);
}

// ---------------------------------------------------------------------------
// Host: replicate numpy's SCALINGS bit-for-bit with double libm.
// ---------------------------------------------------------------------------
static void compute_scalings(ScalArr& a) {
    double growth = exp((log(2048.0) - log(16.0)) / 15.0);
    for (int l = 0; l < NUM_LEVELS; ++l)
        a.s[l] = (float)floor(16.0 * pow(growth, (double)l));
}

extern "C" void kernel_launch(void* const* d_in, const int* in_sizes, int n_in,
                              void* d_out, int out_size) {
    const float* x  = (const float*)d_in[0];
    const float* ht = (const float*)d_in[1];
    float* out = (float*)d_out;

    ScalArr sc;
    compute_scalings(sc);

    combo1_kernel<<<HIST_BLOCKS + R1_BLOCKS, 256>>>(x, ht);
    combo2_kernel<<<SCAN_BLOCKS + R2_BLOCKS1024, 1024>>>(ht);
    combo3_kernel<<<SCAT_BLOCKS + R3_BLOCKS, 256>>>(x, ht);
    hashenc_kernel<<<N_POINTS / 256, 256>>>(out, sc);
}